// round 11
// baseline (speedup 1.0000x reference)
#include <cuda_runtime.h>
#include <cuda_fp16.h>
#include <math_constants.h>
#include <cstdint>

#define BSZ     2
#define NHEAD   16
#define HDIM    64
#define SEQ     2048
#define EMB     1024
#define MROWS   (BSZ * SEQ)          // 4096

// ---------------------------------------------------------------------------
// Scratch
// ---------------------------------------------------------------------------
__device__ __half g_x0[MROWS * EMB];   // query fp16
__device__ __half g_x1[MROWS * EMB];   // key fp16
__device__ __half g_x2[MROWS * EMB];   // value fp16
__device__ __half g_w0[EMB * EMB];     // Wq fp16
__device__ __half g_w1[EMB * EMB];
__device__ __half g_w2[EMB * EMB];
__device__ __half g_w3[EMB * EMB];     // Wo fp16
__device__ __half g_q[MROWS * EMB];
__device__ __half g_k[MROWS * EMB];
__device__ __half g_v[MROWS * EMB];
__device__ __half g_o[MROWS * EMB];

// ---------------------------------------------------------------------------
// Helpers
// ---------------------------------------------------------------------------
__device__ __forceinline__ uint32_t packh2(float a, float b) {
    __half2 h = __floats2half2_rn(a, b);
    return *(uint32_t*)&h;
}
__device__ __forceinline__ uint32_t smaddr(const void* p) {
    return (uint32_t)__cvta_generic_to_shared(p);
}
__device__ __forceinline__ void ldsm4(uint32_t& r0, uint32_t& r1,
                                      uint32_t& r2, uint32_t& r3, uint32_t a) {
    asm volatile("ldmatrix.sync.aligned.m8n8.x4.shared.b16 {%0,%1,%2,%3}, [%4];"
                 : "=r"(r0), "=r"(r1), "=r"(r2), "=r"(r3) : "r"(a));
}
__device__ __forceinline__ void ldsm4t(uint32_t& r0, uint32_t& r1,
                                       uint32_t& r2, uint32_t& r3, uint32_t a) {
    asm volatile("ldmatrix.sync.aligned.m8n8.x4.trans.shared.b16 {%0,%1,%2,%3}, [%4];"
                 : "=r"(r0), "=r"(r1), "=r"(r2), "=r"(r3) : "r"(a));
}
__device__ __forceinline__ void cpasync16(uint32_t dst, const void* src) {
    asm volatile("cp.async.cg.shared.global [%0], [%1], 16;" :: "r"(dst), "l"(src));
}
#define CP_COMMIT() asm volatile("cp.async.commit_group;")
#define CP_WAIT1()  asm volatile("cp.async.wait_group 1;")
__device__ __forceinline__ float ex2f(float x) {
    float y;
    asm("ex2.approx.ftz.f32 %0, %1;" : "=f"(y) : "f"(x));
    return y;
}
// D += A*B  (m16n8k16 fp16 in, fp32 acc)
#define MMA_F16(d, a, b0, b1)                                                 \
    asm volatile(                                                             \
        "mma.sync.aligned.m16n8k16.row.col.f32.f16.f16.f32 "                  \
        "{%0,%1,%2,%3}, {%4,%5,%6,%7}, {%8,%9}, {%0,%1,%2,%3};"               \
        : "+f"((d)[0]), "+f"((d)[1]), "+f"((d)[2]), "+f"((d)[3])              \
        : "r"((a)[0]), "r"((a)[1]), "r"((a)[2]), "r"((a)[3]),                 \
          "r"(b0), "r"(b1))

// ---------------------------------------------------------------------------
// fp32 -> fp16 bulk conversion.
// ---------------------------------------------------------------------------
struct ConvArgs { const float* src[7]; __half* dst[7]; };

__global__ __launch_bounds__(256) void convert_f32_f16(ConvArgs a)
{
    const int idx = blockIdx.x * 256 + threadIdx.x;
    int seg, local;
    if (idx < 3 * 1048576) { seg = idx >> 20;              local = idx & (1048576 - 1); }
    else { const int r = idx - 3 * 1048576; seg = 3 + (r >> 18); local = r & (262144 - 1); }
    const float4 v = ((const float4*)a.src[seg])[local];
    ((uint2*)a.dst[seg])[local] = make_uint2(packh2(v.x, v.y), packh2(v.z, v.w));
}

// ---------------------------------------------------------------------------
// FP16 GEMM (NT), K-stage = 64, double-buffered cp.async.
// Y = A * W^T + bias (+centering+clr). blockIdx.z selects operand set.
// Tiles 128x128x64-per-stage, 8 warps (32m x 64n each).
// ---------------------------------------------------------------------------
#define GSTR 72                        // smem row stride (halves): 144B rows
#define GBUF (128 * GSTR)              // halves per operand per stage
#define GBUFB (GBUF * 2)               // bytes
#define G_SMEM_BYTES (4 * GBUF * 2)    // 2 ops x 2 stages = 73728 B

struct GemmArgs {
    const __half* A[3];
    const __half* W[3];
    const float*  bias[3];
    const float*  clr[3];
    void*         Y[3];
};

template<int OUT_HALF>
__global__ __launch_bounds__(256, 2) void gemm_f16(GemmArgs args, int M, int N, int K)
{
    extern __shared__ __half smh[];
    __half* Asm = smh;                 // [2][GBUF]
    __half* Bsm = smh + 2 * GBUF;      // [2][GBUF]

    const int z = blockIdx.z;
    const __half* A = args.A[z];
    const __half* W = args.W[z];
    const float* bias = args.bias[z];
    const float* clr  = args.clr[z];

    const int bm = blockIdx.y * 128;
    const int bn = blockIdx.x * 128;
    const int tid = threadIdx.x;
    const int lane = tid & 31;
    const int wid  = tid >> 5;
    const int wm = (wid >> 1) * 32;
    const int wn = (wid & 1) * 64;
    const int g = lane >> 2;
    const int t = lane & 3;

    // cp.async coords: 4 chunks of 16B per operand per stage per thread
    const int crow = tid >> 3;          // 0..31
    const int ccol = (tid & 7) * 8;     // half offset within 64-half row
    const __half* Ag = A + (size_t)(bm + crow) * K + ccol;
    const __half* Wg = W + (size_t)(bn + crow) * K + ccol;
    const uint32_t sA = smaddr(Asm) + (crow * GSTR + ccol) * 2;
    const uint32_t sB = smaddr(Bsm) + (crow * GSTR + ccol) * 2;

    // ldmatrix fragment base addresses
    const uint32_t a_frag = smaddr(Asm)
        + ((wm + (lane & 15)) * GSTR + (lane >> 4) * 8) * 2;
    const uint32_t b_frag = smaddr(Bsm)
        + ((wn + (lane & 7) + (lane >> 4) * 8) * GSTR + ((lane >> 3) & 1) * 8) * 2;

    float acc[2][8][4];
    #pragma unroll
    for (int m = 0; m < 2; m++)
        #pragma unroll
        for (int n = 0; n < 8; n++)
            #pragma unroll
            for (int c = 0; c < 4; c++) acc[m][n][c] = 0.0f;

    const int NT = K / 64;             // 16

    #define G_ISSUE(kt, buf) {                                                \
        _Pragma("unroll")                                                     \
        for (int i = 0; i < 4; i++) {                                         \
            cpasync16(sA + (buf) * GBUFB + i * (32 * GSTR * 2),               \
                      Ag + (size_t)i * 32 * K + (kt) * 64);                   \
            cpasync16(sB + (buf) * GBUFB + i * (32 * GSTR * 2),               \
                      Wg + (size_t)i * 32 * K + (kt) * 64);                   \
        } }

    G_ISSUE(0, 0); CP_COMMIT();
    G_ISSUE(1, 1); CP_COMMIT();

    int cur = 0;
    for (int kt = 0; kt < NT; kt++) {
        CP_WAIT1();
        __syncthreads();               // stage kt visible to all warps

        const uint32_t ab = a_frag + cur * GBUFB;
        const uint32_t bb = b_frag + cur * GBUFB;
        #pragma unroll
        for (int kk = 0; kk < 4; kk++) {
            uint32_t a[2][4];
            #pragma unroll
            for (int mi = 0; mi < 2; mi++)
                ldsm4(a[mi][0], a[mi][1], a[mi][2], a[mi][3],
                      ab + mi * (16 * GSTR * 2) + kk * 32);
            #pragma unroll
            for (int nj = 0; nj < 4; nj++) {
                uint32_t b0, b1, b2, b3;
                ldsm4(b0, b1, b2, b3, bb + nj * (16 * GSTR * 2) + kk * 32);
                #pragma unroll
                for (int mi = 0; mi < 2; mi++) {
                    MMA_F16(acc[mi][2 * nj],     a[mi], b0, b1);
                    MMA_F16(acc[mi][2 * nj + 1], a[mi], b2, b3);
                }
            }
        }

        __syncthreads();               // reads of buf cur done
        if (kt + 2 < NT) G_ISSUE(kt + 2, cur);
        CP_COMMIT();
        cur ^= 1;
    }

    // ---- epilogue ----
    const int h = blockIdx.x * 2 + (wid & 1);

    #pragma unroll
    for (int m = 0; m < 2; m++) {
        #pragma unroll
        for (int n = 0; n < 8; n++) {
            const int c = bn + wn + n * 8 + 2 * t;
            const float b0 = __ldg(&bias[c]);
            const float b1 = __ldg(&bias[c + 1]);
            acc[m][n][0] += b0; acc[m][n][1] += b1;
            acc[m][n][2] += b0; acc[m][n][3] += b1;
        }
        if (clr) {
            float s0 = 0.0f, s1 = 0.0f;
            #pragma unroll
            for (int n = 0; n < 8; n++) {
                s0 += acc[m][n][0] + acc[m][n][1];
                s1 += acc[m][n][2] + acc[m][n][3];
            }
            s0 += __shfl_xor_sync(0xffffffffu, s0, 1);
            s0 += __shfl_xor_sync(0xffffffffu, s0, 2);
            s1 += __shfl_xor_sync(0xffffffffu, s1, 1);
            s1 += __shfl_xor_sync(0xffffffffu, s1, 2);
            const float mean0 = s0 * (1.0f / 64.0f);
            const float mean1 = s1 * (1.0f / 64.0f);
            #pragma unroll
            for (int n = 0; n < 8; n++) {
                const int d = n * 8 + 2 * t;
                const float c0 = __ldg(&clr[h * 64 + d]);
                const float c1 = __ldg(&clr[h * 64 + d + 1]);
                acc[m][n][0] += c0 - mean0; acc[m][n][1] += c1 - mean0;
                acc[m][n][2] += c0 - mean1; acc[m][n][3] += c1 - mean1;
            }
        }
        const int r0 = bm + wm + m * 16 + g;
        #pragma unroll
        for (int n = 0; n < 8; n++) {
            const int c = bn + wn + n * 8 + 2 * t;
            if (OUT_HALF) {
                __half* Y = (__half*)args.Y[z];
                *(uint32_t*)(Y + (size_t)r0 * N + c) =
                    packh2(acc[m][n][0], acc[m][n][1]);
                *(uint32_t*)(Y + (size_t)(r0 + 8) * N + c) =
                    packh2(acc[m][n][2], acc[m][n][3]);
            } else {
                float* Y = (float*)args.Y[z];
                *(float2*)(Y + (size_t)r0 * N + c) =
                    make_float2(acc[m][n][0], acc[m][n][1]);
                *(float2*)(Y + (size_t)(r0 + 8) * N + c) =
                    make_float2(acc[m][n][2], acc[m][n][3]);
            }
        }
    }
}

// ---------------------------------------------------------------------------
// FP16 flash attention, cp.async 3-stage K/V ring, Q fragments hoisted,
// softmax in log2 domain. Block: 128q x 64k, 8 warps (16 q-rows each).
// ---------------------------------------------------------------------------
#define FQ 72
#define FA_Q  (128 * FQ)
#define FA_KV (64 * FQ)
#define FA_SMEM_BYTES ((FA_Q + 6 * FA_KV) * 2 + 3 * 64)
#define CSC 0.18033688011112042f      // 0.125 * log2(e)

__global__ __launch_bounds__(256, 2) void flash_f16(
    const __half* __restrict__ Q, const __half* __restrict__ K,
    const __half* __restrict__ V, const unsigned char* __restrict__ mask,
    __half* __restrict__ O)
{
    extern __shared__ __half smh[];
    __half* Qs = smh;
    __half* Ks = smh + FA_Q;
    __half* Vs = smh + FA_Q + 3 * FA_KV;
    unsigned char* msk = (unsigned char*)(smh + FA_Q + 6 * FA_KV);

    const int qt = blockIdx.x;
    const int h  = blockIdx.y;
    const int b  = blockIdx.z;
    const int tid  = threadIdx.x;
    const int lane = tid & 31;
    const int wid  = tid >> 5;
    const int g = lane >> 2;
    const int t = lane & 3;
    const int wq = wid * 16;

    const __half* Qb = Q + ((size_t)b * SEQ + qt * 128) * EMB + h * HDIM;
    const __half* Kb = K + (size_t)b * SEQ * EMB + h * HDIM;
    const __half* Vb = V + (size_t)b * SEQ * EMB + h * HDIM;
    const unsigned char* mb = mask + (size_t)b * SEQ;

    const int lr = tid >> 3;
    const int lc = (tid & 7) * 8;

    #pragma unroll
    for (int i = 0; i < 4; i++)
        cpasync16(smaddr(Qs) + (((lr + i * 32) * FQ + lc) * 2),
                  Qb + (size_t)(lr + i * 32) * EMB + lc);

    #define F_ISSUE(kt, buf) {                                                    \
        const __half* Kt = Kb + (size_t)(kt) * 64 * EMB;                          \
        const __half* Vt = Vb + (size_t)(kt) * 64 * EMB;                          \
        const uint32_t ko = smaddr(Ks) + (buf) * (FA_KV * 2);                     \
        const uint32_t vo = smaddr(Vs) + (buf) * (FA_KV * 2);                     \
        cpasync16(ko + (lr * FQ + lc) * 2,        Kt + (size_t)lr * EMB + lc);    \
        cpasync16(ko + ((lr + 32) * FQ + lc) * 2, Kt + (size_t)(lr + 32) * EMB + lc); \
        cpasync16(vo + (lr * FQ + lc) * 2,        Vt + (size_t)lr * EMB + lc);    \
        cpasync16(vo + ((lr + 32) * FQ + lc) * 2, Vt + (size_t)(lr + 32) * EMB + lc); \
        if (tid < 4)                                                              \
            cpasync16(smaddr(msk) + (buf) * 64 + tid * 16, mb + (kt) * 64 + tid * 16); }

    F_ISSUE(0, 0); CP_COMMIT();
    F_ISSUE(1, 1); CP_COMMIT();
    CP_WAIT1(); __syncthreads();

    uint32_t qf[4][4];
    {
        const uint32_t q_base = smaddr(Qs)
            + ((wq + (lane & 15)) * FQ + (lane >> 4) * 8) * 2;
        #pragma unroll
        for (int kk = 0; kk < 4; kk++)
            ldsm4(qf[kk][0], qf[kk][1], qf[kk][2], qf[kk][3], q_base + kk * 32);
    }

    const uint32_t k_lane = (((lane & 7) + (lane >> 4) * 8) * FQ
                             + ((lane >> 3) & 1) * 8) * 2;
    const uint32_t v_lane = (((lane & 7) + ((lane >> 3) & 1) * 8) * FQ
                             + (lane >> 4) * 8) * 2;

    float o_[8][4];
    float mrow[2], lrow[2];
    #pragma unroll
    for (int n = 0; n < 8; n++)
        #pragma unroll
        for (int c = 0; c < 4; c++) o_[n][c] = 0.0f;
    mrow[0] = mrow[1] = -CUDART_INF_F;
    lrow[0] = lrow[1] = 0.0f;

    const int NT = SEQ / 64;
    int cur = 0, ins = 2;
    for (int kt = 0; kt < NT; kt++) {
        const uint32_t kb = smaddr(Ks) + cur * (FA_KV * 2) + k_lane;
        const uint32_t vb = smaddr(Vs) + cur * (FA_KV * 2) + v_lane;
        const unsigned char* mskc = msk + cur * 64;

        float s[8][4];
        #pragma unroll
        for (int n = 0; n < 8; n++)
            #pragma unroll
            for (int c = 0; c < 4; c++) s[n][c] = 0.0f;

        #pragma unroll
        for (int kk = 0; kk < 4; kk++) {
            #pragma unroll
            for (int nj = 0; nj < 4; nj++) {
                uint32_t b0, b1, b2, b3;
                ldsm4(b0, b1, b2, b3, kb + nj * (16 * FQ * 2) + kk * 32);
                MMA_F16(s[2 * nj],     qf[kk], b0, b1);
                MMA_F16(s[2 * nj + 1], qf[kk], b2, b3);
            }
        }

        #pragma unroll
        for (int n = 0; n < 8; n++) {
            const float m0 = mskc[n * 8 + 2 * t]     ? -CUDART_INF_F : 0.0f;
            const float m1 = mskc[n * 8 + 2 * t + 1] ? -CUDART_INF_F : 0.0f;
            s[n][0] = s[n][0] * CSC + m0;
            s[n][1] = s[n][1] * CSC + m1;
            s[n][2] = s[n][2] * CSC + m0;
            s[n][3] = s[n][3] * CSC + m1;
        }

        float mx0 = -CUDART_INF_F, mx1 = -CUDART_INF_F;
        #pragma unroll
        for (int n = 0; n < 8; n++) {
            mx0 = fmaxf(mx0, fmaxf(s[n][0], s[n][1]));
            mx1 = fmaxf(mx1, fmaxf(s[n][2], s[n][3]));
        }
        mx0 = fmaxf(mx0, __shfl_xor_sync(0xffffffffu, mx0, 1));
        mx0 = fmaxf(mx0, __shfl_xor_sync(0xffffffffu, mx0, 2));
        mx1 = fmaxf(mx1, __shfl_xor_sync(0xffffffffu, mx1, 1));
        mx1 = fmaxf(mx1, __shfl_xor_sync(0xffffffffu, mx1, 2));

        const float mn0 = fmaxf(mrow[0], mx0);
        const float mn1 = fmaxf(mrow[1], mx1);
        const float cr0 = ex2f(mrow[0] - mn0);
        const float cr1 = ex2f(mrow[1] - mn1);

        float rs0 = 0.0f, rs1 = 0.0f;
        #pragma unroll
        for (int n = 0; n < 8; n++) {
            s[n][0] = ex2f(s[n][0] - mn0);
            s[n][1] = ex2f(s[n][1] - mn0);
            s[n][2] = ex2f(s[n][2] - mn1);
            s[n][3] = ex2f(s[n][3] - mn1);
            rs0 += s[n][0] + s[n][1];
            rs1 += s[n][2] + s[n][3];
        }
        rs0 += __shfl_xor_sync(0xffffffffu, rs0, 1);
        rs0 += __shfl_xor_sync(0xffffffffu, rs0, 2);
        rs1 += __shfl_xor_sync(0xffffffffu, rs1, 1);
        rs1 += __shfl_xor_sync(0xffffffffu, rs1, 2);

        lrow[0] = lrow[0] * cr0 + rs0;
        lrow[1] = lrow[1] * cr1 + rs1;
        mrow[0] = mn0; mrow[1] = mn1;

        #pragma unroll
        for (int n = 0; n < 8; n++) {
            o_[n][0] *= cr0; o_[n][1] *= cr0;
            o_[n][2] *= cr1; o_[n][3] *= cr1;
        }

        uint32_t ph[4][4];
        #pragma unroll
        for (int kk = 0; kk < 4; kk++) {
            ph[kk][0] = packh2(s[2 * kk][0],     s[2 * kk][1]);
            ph[kk][1] = packh2(s[2 * kk][2],     s[2 * kk][3]);
            ph[kk][2] = packh2(s[2 * kk + 1][0], s[2 * kk + 1][1]);
            ph[kk][3] = packh2(s[2 * kk + 1][2], s[2 * kk + 1][3]);
        }

        #pragma unroll
        for (int kk = 0; kk < 4; kk++) {
            #pragma unroll
            for (int nj = 0; nj < 4; nj++) {
                uint32_t b0, b1, b2, b3;
                ldsm4t(b0, b1, b2, b3, vb + kk * (16 * FQ * 2) + nj * 32);
                MMA_F16(o_[2 * nj],     ph[kk], b0, b1);
                MMA_F16(o_[2 * nj + 1], ph[kk], b2, b3);
            }
        }

        if (kt + 2 < NT) F_ISSUE(kt + 2, ins);
        CP_COMMIT();
        CP_WAIT1();
        __syncthreads();
        cur = (cur == 2) ? 0 : cur + 1;
        ins = (ins == 2) ? 0 : ins + 1;
    }

    const float inv0 = 1.0f / lrow[0];
    const float inv1 = 1.0f / lrow[1];
    __half* Ob = O + ((size_t)b * SEQ + qt * 128) * EMB + h * HDIM;
    #pragma unroll
    for (int n = 0; n < 8; n++) {
        const int d = n * 8 + 2 * t;
        *(uint32_t*)(Ob + (size_t)(wq + g) * EMB + d) =
            packh2(o_[n][0] * inv0, o_[n][1] * inv0);
        *(uint32_t*)(Ob + (size_t)(wq + g + 8) * EMB + d) =
            packh2(o_[n][2] * inv1, o_[n][3] * inv1);
    }
}

// ---------------------------------------------------------------------------
// Launch
// ---------------------------------------------------------------------------
extern "C" void kernel_launch(void* const* d_in, const int* in_sizes, int n_in,
                              void* d_out, int out_size)
{
    const float* query = (const float*)d_in[0];
    const float* key   = (const float*)d_in[1];
    const float* value = (const float*)d_in[2];
    const unsigned char* kpm = (const unsigned char*)d_in[3];
    const float* Wq = (const float*)d_in[4];
    const float* bq = (const float*)d_in[5];
    const float* Wk = (const float*)d_in[6];
    const float* bk = (const float*)d_in[7];
    const float* Wv = (const float*)d_in[8];
    const float* bv = (const float*)d_in[9];
    const float* Wo = (const float*)d_in[10];
    const float* bo = (const float*)d_in[11];
    const float* clrq = (const float*)d_in[12];
    const float* clrk = (const float*)d_in[13];
    float* out = (float*)d_out;

    __half *x0, *x1, *x2, *w0, *w1, *w2, *w3, *gq, *gk, *gv, *go;
    cudaGetSymbolAddress((void**)&x0, g_x0);
    cudaGetSymbolAddress((void**)&x1, g_x1);
    cudaGetSymbolAddress((void**)&x2, g_x2);
    cudaGetSymbolAddress((void**)&w0, g_w0);
    cudaGetSymbolAddress((void**)&w1, g_w1);
    cudaGetSymbolAddress((void**)&w2, g_w2);
    cudaGetSymbolAddress((void**)&w3, g_w3);
    cudaGetSymbolAddress((void**)&gq, g_q);
    cudaGetSymbolAddress((void**)&gk, g_k);
    cudaGetSymbolAddress((void**)&gv, g_v);
    cudaGetSymbolAddress((void**)&go, g_o);

    cudaFuncSetAttribute(flash_f16, cudaFuncAttributeMaxDynamicSharedMemorySize,
                         FA_SMEM_BYTES);
    cudaFuncSetAttribute(gemm_f16<1>, cudaFuncAttributeMaxDynamicSharedMemorySize,
                         G_SMEM_BYTES);
    cudaFuncSetAttribute(gemm_f16<0>, cudaFuncAttributeMaxDynamicSharedMemorySize,
                         G_SMEM_BYTES);

    // 1) convert everything to fp16
    ConvArgs ca;
    ca.src[0] = query; ca.src[1] = key; ca.src[2] = value;
    ca.src[3] = Wq; ca.src[4] = Wk; ca.src[5] = Wv; ca.src[6] = Wo;
    ca.dst[0] = x0; ca.dst[1] = x1; ca.dst[2] = x2;
    ca.dst[3] = w0; ca.dst[4] = w1; ca.dst[5] = w2; ca.dst[6] = w3;
    convert_f32_f16<<<16384, 256>>>(ca);

    // 2) fused QKV projections (+ centering/clr on Q,K)
    GemmArgs ga;
    ga.A[0] = x0; ga.A[1] = x1; ga.A[2] = x2;
    ga.W[0] = w0; ga.W[1] = w1; ga.W[2] = w2;
    ga.bias[0] = bq; ga.bias[1] = bk; ga.bias[2] = bv;
    ga.clr[0] = clrq; ga.clr[1] = clrk; ga.clr[2] = nullptr;
    ga.Y[0] = gq; ga.Y[1] = gk; ga.Y[2] = gv;
    gemm_f16<1><<<dim3(EMB / 128, MROWS / 128, 3), 256, G_SMEM_BYTES>>>(
        ga, MROWS, EMB, EMB);

    // 3) attention
    flash_f16<<<dim3(SEQ / 128, NHEAD, BSZ), 256, FA_SMEM_BYTES>>>(
        gq, gk, gv, kpm, go);

    // 4) output projection (fp32 out)
    GemmArgs gb;
    gb.A[0] = go; gb.W[0] = w3; gb.bias[0] = bo; gb.clr[0] = nullptr; gb.Y[0] = out;
    gb.A[1] = gb.A[2] = nullptr; gb.W[1] = gb.W[2] = nullptr;
    gb.bias[1] = gb.bias[2] = nullptr; gb.clr[1] = gb.clr[2] = nullptr;
    gb.Y[1] = gb.Y[2] = nullptr;
    gemm_f16<0><<<dim3(EMB / 128, MROWS / 128, 1), 256, G_SMEM_BYTES>>>(
        gb, MROWS, EMB, EMB);
}